// round 3
// baseline (speedup 1.0000x reference)
#include <cuda_runtime.h>
#include <cstdint>

#define BB 2
#define SS 1024
#define CC 1024
#define HH 16
#define DIMP 240
#define NROT 144

// scratch (device globals: no allocation allowed)
__device__ float g_Q[BB*HH*SS*8];    // per (b,h,q): qrot3, qdist3, code, pad
__device__ float g_K[BB*HH*SS*12];   // per (b,h,k): krot3, kdist3, v3, code, pad2
__device__ float g_att[BB*SS*48];    // (b,s, h*3+i) pre-output

__device__ __forceinline__ float warp_sum(float v){
  #pragma unroll
  for (int o = 16; o > 0; o >>= 1) v += __shfl_xor_sync(0xffffffffu, v, o);
  return v;
}

// ---------------------------------------------------------------------------
// Kernel 1: layernorm + projection + per-token rotation, 8 s-rows per block
// ---------------------------------------------------------------------------
__global__ __launch_bounds__(256) void k1_proj(
    const float* __restrict__ s, const float* __restrict__ rot,
    const float* __restrict__ trans, const float* __restrict__ ln_w,
    const float* __restrict__ w_proj,
    const int* __restrict__ amask,
    const int* __restrict__ seq_id, const int* __restrict__ chain_id)
{
  __shared__ float ns_s[CC*9];        // [c][r], stride 9 (conflict-free)
  __shared__ float p_s[8*DIMP];       // [r][d]
  __shared__ float rot_s[8*9];
  __shared__ float trans_s[8*3];
  __shared__ int   code_s[8*2];       // qcode, kcode per row

  const int tid  = threadIdx.x;
  const int lane = tid & 31;
  const int w    = tid >> 5;
  const int sbase = blockIdx.x * 8;   // 256 blocks * 8 rows = 2048

  if (tid < 72) rot_s[tid]   = rot[(size_t)sbase*9 + tid];
  if (tid < 24) trans_s[tid] = trans[(size_t)sbase*3 + tid];
  if (tid < 8) {
    int row = sbase + tid;
    int q = (chain_id[row] << 16) | (seq_id[row] & 0xFFFF);
    code_s[tid*2]   = q;
    code_s[tid*2+1] = (amask[row] != 0) ? q : -1;
  }

  // ---- phase A: layernorm, one warp per row ----
  {
    int row = sbase + w;
    const float* sr = s + (size_t)row * CC;
    float4 buf[8];
    float sum = 0.f, sq = 0.f;
    #pragma unroll
    for (int i = 0; i < 8; i++) {
      float4 v = *(const float4*)(sr + i*128 + lane*4);
      buf[i] = v;
      sum += v.x + v.y + v.z + v.w;
      sq  += v.x*v.x + v.y*v.y + v.z*v.z + v.w*v.w;
    }
    sum = warp_sum(sum); sq = warp_sum(sq);
    float mean = sum * (1.f/CC);
    float var  = sq  * (1.f/CC) - mean*mean;
    float rstd = rsqrtf(var + 1e-5f);
    #pragma unroll
    for (int i = 0; i < 8; i++) {
      int c0 = i*128 + lane*4;
      float4 lw = *(const float4*)(ln_w + c0);
      ns_s[(c0+0)*9 + w] = (buf[i].x - mean)*rstd*lw.x;
      ns_s[(c0+1)*9 + w] = (buf[i].y - mean)*rstd*lw.y;
      ns_s[(c0+2)*9 + w] = (buf[i].z - mean)*rstd*lw.z;
      ns_s[(c0+3)*9 + w] = (buf[i].w - mean)*rstd*lw.w;
    }
  }
  __syncthreads();

  // ---- phase B: p[r][d] = sum_c ns[r][c] * w_proj[d][c] ----
  // warp w owns d in [w*30, w*30+30); 5 outer iters x 6 d's, 8-row register tile
  const int dbase = w * 30;
  for (int jo = 0; jo < 5; jo++) {
    float acc[6][8];
    #pragma unroll
    for (int j = 0; j < 6; j++)
      #pragma unroll
      for (int r = 0; r < 8; r++) acc[j][r] = 0.f;

    for (int ci = 0; ci < 32; ci++) {
      int c = ci*32 + lane;
      float nv[8];
      #pragma unroll
      for (int r = 0; r < 8; r++) nv[r] = ns_s[c*9 + r];
      #pragma unroll
      for (int j = 0; j < 6; j++) {
        float wv = w_proj[(size_t)(dbase + jo*6 + j)*CC + c];
        #pragma unroll
        for (int r = 0; r < 8; r++) acc[j][r] += wv * nv[r];
      }
    }
    #pragma unroll
    for (int j = 0; j < 6; j++) {
      #pragma unroll
      for (int r = 0; r < 8; r++) {
        float v = warp_sum(acc[j][r]);
        if (lane == 0) p_s[r*DIMP + dbase + jo*6 + j] = v;
      }
    }
  }
  __syncthreads();

  // ---- phase C: rotate 3-vectors, scatter to attention layout ----
  for (int idx = tid; idx < 640; idx += 256) {
    int r = idx / 80, v = idx - r*80;
    int row = sbase + r;
    int b = row >> 10, sl = row & 1023;
    const float* R = &rot_s[r*9];
    if (v < 48) {
      const float* pv = &p_s[r*DIMP + v*3];
      float x = pv[0], y = pv[1], z = pv[2];
      float o0 = R[0]*x + R[1]*y + R[2]*z;
      float o1 = R[3]*x + R[4]*y + R[5]*z;
      float o2 = R[6]*x + R[7]*y + R[8]*z;
      if (v < 16) {
        float* q = &g_Q[((size_t)((b*HH + v)*SS) + sl)*8];
        q[0] = o0; q[1] = o1; q[2] = o2;
      } else if (v < 32) {
        float* kk = &g_K[((size_t)((b*HH + (v-16))*SS) + sl)*12];
        kk[0] = o0; kk[1] = o1; kk[2] = o2;
      } else {
        float* kk = &g_K[((size_t)((b*HH + (v-32))*SS) + sl)*12];
        kk[6] = o0; kk[7] = o1; kk[8] = o2;
      }
    } else {
      int d = v - 48;
      const float* pv = &p_s[r*DIMP + NROT + d*3];
      float x = pv[0], y = pv[1], z = pv[2];
      const float* T = &trans_s[r*3];
      float o0 = R[0]*x + R[1]*y + R[2]*z + T[0];
      float o1 = R[3]*x + R[4]*y + R[5]*z + T[1];
      float o2 = R[6]*x + R[7]*y + R[8]*z + T[2];
      if (d < 16) {
        float* q = &g_Q[((size_t)((b*HH + d)*SS) + sl)*8];
        q[3] = o0; q[4] = o1; q[5] = o2;
        q[6] = __int_as_float(code_s[r*2]);
      } else {
        float* kk = &g_K[((size_t)((b*HH + (d-16))*SS) + sl)*12];
        kk[3] = o0; kk[4] = o1; kk[5] = o2;
        kk[9] = __int_as_float(code_s[r*2+1]);
      }
    }
  }
}

// ---------------------------------------------------------------------------
// Kernel 2: geometric attention. block = (b, h, 128-q tile), warp = 16 q rows
// processed as two 8-row register tiles; lane strides over k. No max-subtract
// (scores bounded; masked -> -1e30 -> exp underflows to 0).
// ---------------------------------------------------------------------------
__global__ __launch_bounds__(256) void k2_attn(
    const float* __restrict__ rot,
    const float* __restrict__ dist_scale, const float* __restrict__ rot_scale,
    const int* __restrict__ amask)
{
  const int qt   = blockIdx.x & 7;
  const int h    = (blockIdx.x >> 3) & 15;
  const int b    = blockIdx.x >> 7;
  const int lane = threadIdx.x & 31;
  const int w    = threadIdx.x >> 5;

  const float INV_SQRT3 = 0.57735026918962576f;
  float rx = rot_scale[h], dx = dist_scale[h];
  float rw = (rx > 20.f ? rx : log1pf(__expf(rx))) * INV_SQRT3;   // softplus
  float dw = (dx > 20.f ? dx : log1pf(__expf(dx))) * INV_SQRT3;

  const float* Kb = g_K + (size_t)((b*HH + h)*SS)*12;
  const float* Qb = g_Q + (size_t)((b*HH + h)*SS)*8;

  const int qwarpbase = qt*128 + w*16;
  for (int chunk = 0; chunk < 2; chunk++) {
    const int q0 = qwarpbase + chunk*8;
    float qr0[8], qr1[8], qr2[8], qd0[8], qd1[8], qd2[8];
    int qcode[8], qch[8];
    #pragma unroll
    for (int r = 0; r < 8; r++) {
      const float* qp = Qb + (size_t)(q0 + r)*8;
      float4 a  = *(const float4*)qp;
      float4 bq = *(const float4*)(qp + 4);
      qr0[r] = a.x;  qr1[r] = a.y;  qr2[r] = a.z;
      qd0[r] = a.w;  qd1[r] = bq.x; qd2[r] = bq.y;
      qcode[r] = __float_as_int(bq.z);
      qch[r]   = qcode[r] >> 16;
    }
    float l[8], a0[8], a1[8], a2[8];
    #pragma unroll
    for (int r = 0; r < 8; r++) { l[r]=0.f; a0[r]=0.f; a1[r]=0.f; a2[r]=0.f; }

    for (int ki = 0; ki < 32; ki++) {
      const int kk = ki*32 + lane;
      const float* kp = Kb + (size_t)kk*12;
      float4 kA = *(const float4*)kp;          // krx kry krz kdx
      float4 kB = *(const float4*)(kp + 4);    // kdy kdz vx  vy
      float2 kC = *(const float2*)(kp + 8);    // vz  code
      int kcode  = __float_as_int(kC.y);
      int kchain = kcode >> 16;
      #pragma unroll
      for (int r = 0; r < 8; r++) {
        float rt  = qr0[r]*kA.x + qr1[r]*kA.y + qr2[r]*kA.z;
        float ddx = qd0[r]-kA.w, ddy = qd1[r]-kB.x, ddz = qd2[r]-kB.y;
        float d2  = ddx*ddx + ddy*ddy + ddz*ddz;
        float sc  = rt*rw - sqrtf(d2)*dw;
        sc += (kcode == qcode[r]) ? 1.0f
             : (kchain == qch[r] ? 0.0f : -1e30f);
        float p = __expf(sc);
        l[r]  += p;
        a0[r] += p*kB.z; a1[r] += p*kB.w; a2[r] += p*kC.x;
      }
    }
    #pragma unroll
    for (int r = 0; r < 8; r++) {
      float L  = warp_sum(l[r]);
      float A0 = warp_sum(a0[r]);
      float A1 = warp_sum(a1[r]);
      float A2 = warp_sum(a2[r]);
      if (lane == r) {
        int q = q0 + r;
        float inv = 1.f / L;
        float o0 = A0*inv, o1 = A1*inv, o2 = A2*inv;
        int row = b*SS + q;
        const float* R = rot + (size_t)row*9;
        // out_i = sum_j rot[j][i] * o_j   (transpose rotation back)
        float u0 = R[0]*o0 + R[3]*o1 + R[6]*o2;
        float u1 = R[1]*o0 + R[4]*o1 + R[7]*o2;
        float u2 = R[2]*o0 + R[5]*o1 + R[8]*o2;
        float mk = (amask[row] != 0) ? 1.f : 0.f;
        float* op = g_att + (size_t)row*48 + h*3;
        op[0] = u0*mk; op[1] = u1*mk; op[2] = u2*mk;
      }
    }
  }
}

// ---------------------------------------------------------------------------
// Kernel 3: out[b,s,c] = sum_d att[b,s,d] * w_out[c,d]
// block = 128 s-rows x 64 c-cols, both operand tiles transposed in smem
// ---------------------------------------------------------------------------
__global__ __launch_bounds__(256) void k3_out(
    const float* __restrict__ w_out, float* __restrict__ out)
{
  __shared__ float w_s[48*64];    // [d][c]
  __shared__ float a_s[48*128];   // [d][r]
  const int tid = threadIdx.x;
  const int ct = blockIdx.x & 15, st = blockIdx.x >> 4;
  const int cb = ct*64, sb = st*128;

  for (int idx = tid; idx < 64*48; idx += 256) {
    int c = idx/48, d = idx - c*48;
    w_s[d*64 + c] = w_out[(size_t)(cb + c)*48 + d];
  }
  for (int idx = tid; idx < 128*48; idx += 256) {
    int r = idx/48, d = idx - r*48;
    a_s[d*128 + r] = g_att[(size_t)(sb + r)*48 + d];
  }
  __syncthreads();

  const int tx = tid & 15, ty = tid >> 4;    // 16 c-groups x 16 s-groups
  float acc[8][4];
  #pragma unroll
  for (int i = 0; i < 8; i++)
    #pragma unroll
    for (int j = 0; j < 4; j++) acc[i][j] = 0.f;

  #pragma unroll 4
  for (int d = 0; d < 48; d++) {
    float4 wv = *(const float4*)&w_s[d*64 + tx*4];
    float4 aA = *(const float4*)&a_s[d*128 + ty*8];
    float4 aB = *(const float4*)&a_s[d*128 + ty*8 + 4];
    float av[8] = {aA.x, aA.y, aA.z, aA.w, aB.x, aB.y, aB.z, aB.w};
    #pragma unroll
    for (int i = 0; i < 8; i++) {
      acc[i][0] += av[i]*wv.x;
      acc[i][1] += av[i]*wv.y;
      acc[i][2] += av[i]*wv.z;
      acc[i][3] += av[i]*wv.w;
    }
  }
  #pragma unroll
  for (int i = 0; i < 8; i++) {
    float4 res = make_float4(acc[i][0], acc[i][1], acc[i][2], acc[i][3]);
    *(float4*)&out[(size_t)(sb + ty*8 + i)*1024 + cb + tx*4] = res;
  }
}

// ---------------------------------------------------------------------------
extern "C" void kernel_launch(void* const* d_in, const int* in_sizes, int n_in,
                              void* d_out, int out_size)
{
  const float* s          = (const float*)d_in[0];
  const float* rot        = (const float*)d_in[1];
  const float* trans      = (const float*)d_in[2];
  const float* ln_w       = (const float*)d_in[3];
  const float* w_proj     = (const float*)d_in[4];
  const float* w_out      = (const float*)d_in[5];
  const float* dist_scale = (const float*)d_in[6];
  const float* rot_scale  = (const float*)d_in[7];
  const int* am           = (const int*)d_in[8];
  const int* seq_id       = (const int*)d_in[9];
  const int* chain_id     = (const int*)d_in[10];
  float* out = (float*)d_out;

  k1_proj<<<256, 256>>>(s, rot, trans, ln_w, w_proj, am, seq_id, chain_id);
  k2_attn<<<256, 256>>>(rot, dist_scale, rot_scale, am);
  k3_out <<<16*16, 256>>>(w_out, out);
}